// round 14
// baseline (speedup 1.0000x reference)
#include <cuda_runtime.h>
#include <cstdint>

#define NPTS 16384
#define NB   8
#define NP   1024
#define CIN  32
#define CSZ  8                 // FPS cluster size (CTAs per batch)
#define SLICE (NPTS/CSZ)       // 2048 points per CTA
#define FTH  512               // FPS threads per CTA
#define PPT  (SLICE/FTH)       // 4 points per thread
#define NW   (FTH/32)          // 16 warps
#define HALF (NPTS/2)

// ---------------- scratch (static __device__, no allocation) ----------------
__device__ float g_xs[NB*NPTS], g_ys[NB*NPTS], g_zs[NB*NPTS], g_xn[NB*NPTS];
__device__ float g_qx[NB*NP], g_qy[NB*NP], g_qz[NB*NP], g_qn[NB*NP];
__device__ int   g_idx0[NB*NP*16];
__device__ int   g_idx1[NB*NP*32];
__device__ float g_w0p[32*36];   // branch0 L1 weights padded 35->36
__device__ float g_w1p[64*36];   // branch1 L1 weights padded 35->36
// half-scan ball query buffers: [pair][half]
__device__ int   g_c0h[NB*NP*2], g_c1h[NB*NP*2];
__device__ int   g_o0h[NB*NP*2*16];
__device__ int   g_o1h[NB*NP*2*32];

// ---------------- packed f32x2 helpers (Blackwell) ----------------
__device__ __forceinline__ unsigned long long pk2(float a, float b){
  unsigned long long r; asm("mov.b64 %0,{%1,%2};" : "=l"(r) : "f"(a), "f"(b)); return r;
}
__device__ __forceinline__ void upk2(unsigned long long v, float& a, float& b){
  asm("mov.b64 {%0,%1},%2;" : "=f"(a), "=f"(b) : "l"(v));
}
__device__ __forceinline__ unsigned long long add2(unsigned long long a, unsigned long long b){
  unsigned long long r; asm("add.rn.f32x2 %0,%1,%2;" : "=l"(r) : "l"(a), "l"(b)); return r;
}
__device__ __forceinline__ unsigned long long mul2(unsigned long long a, unsigned long long b){
  unsigned long long r; asm("mul.rn.f32x2 %0,%1,%2;" : "=l"(r) : "l"(a), "l"(b)); return r;
}
__device__ __forceinline__ unsigned long long fma2(unsigned long long a, unsigned long long b,
                                                  unsigned long long c){
  unsigned long long r; asm("fma.rn.f32x2 %0,%1,%2,%3;" : "=l"(r) : "l"(a), "l"(b), "l"(c));
  return r;
}

// ---------------- cluster / smem helpers ----------------
__device__ __forceinline__ uint32_t smem_u32(const void* p){
  return (uint32_t)__cvta_generic_to_shared(p);
}
__device__ __forceinline__ uint32_t mapa_rank(uint32_t laddr, uint32_t rank){
  uint32_t r; asm("mapa.shared::cluster.u32 %0, %1, %2;" : "=r"(r) : "r"(laddr), "r"(rank));
  return r;
}
__device__ __forceinline__ void st_cl_v4(uint32_t addr, unsigned a, unsigned b,
                                         unsigned c, unsigned d){
  asm volatile("st.shared::cluster.v4.b32 [%0],{%1,%2,%3,%4};"
               :: "r"(addr), "r"(a), "r"(b), "r"(c), "r"(d) : "memory");
}
__device__ __forceinline__ void cluster_sync_all(){
  asm volatile("barrier.cluster.arrive.aligned;" ::: "memory");
  asm volatile("barrier.cluster.wait.aligned;" ::: "memory");
}
__device__ __forceinline__ uint32_t ctarank(){
  uint32_t r; asm("mov.u32 %0, %%cluster_ctarank;" : "=r"(r)); return r;
}

// ---------------- prep: AoS->SoA + squared norms ----------------
__global__ void prep_soa(const float* __restrict__ xyz){
  int i = blockIdx.x*blockDim.x + threadIdx.x;
  if (i >= NB*NPTS) return;
  float x = xyz[3*i+0], y = xyz[3*i+1], z = xyz[3*i+2];
  g_xs[i]=x; g_ys[i]=y; g_zs[i]=z;
  g_xn[i] = __fadd_rn(__fadd_rn(__fmul_rn(x,x), __fmul_rn(y,y)), __fmul_rn(z,z));
}

// ---------------- prep: pad L1 weight rows 35 -> 36 ----------------
__global__ void prep_w(const float* __restrict__ w00, const float* __restrict__ w10){
  int t = threadIdx.x;
  for (int i=t; i<32*36; i+=256){ int o=i/36, c=i-o*36; g_w0p[i] = (c<35) ? w00[o*35+c] : 0.f; }
  for (int i=t; i<64*36; i+=256){ int o=i/36, c=i-o*36; g_w1p[i] = (c<35) ? w10[o*35+c] : 0.f; }
}

// ---------------- FPS: 8-CTA cluster, HW cluster-barrier exchange (R13 winner) ----------------
__global__ void __cluster_dims__(CSZ,1,1) __launch_bounds__(FTH,1)
fps_kernel(float* __restrict__ newxyz){
  const int b = blockIdx.x / CSZ;
  const uint32_t rank = ctarank();
  const float* __restrict__ xs = g_xs + b*NPTS;
  const float* __restrict__ ys = g_ys + b*NPTS;
  const float* __restrict__ zs = g_zs + b*NPTS;
  const int t = threadIdx.x;
  const int lane = t & 31, wid = t >> 5;        // wid 0..15
  const int gi0 = rank*SLICE + t*PPT;           // 4 consecutive point indices

  __shared__ uint4 s_c4[NW];        // per-warp candidates {vb, x, y, z}
  __shared__ uint4 s_ex[2][CSZ];    // exchange slots [par][rank] {vb, x, y, z}

  // register-resident point coords (4 pts/thread)
  const float4 X = *reinterpret_cast<const float4*>(xs + gi0);
  const float4 Y = *reinterpret_cast<const float4*>(ys + gi0);
  const float4 Z = *reinterpret_cast<const float4*>(zs + gi0);
  const unsigned long long PX0 = pk2(X.x, X.y), PX1 = pk2(X.z, X.w);
  const unsigned long long PY0 = pk2(Y.x, Y.y), PY1 = pk2(Y.z, Y.w);
  const unsigned long long PZ0 = pk2(Z.x, Z.y), PZ1 = pk2(Z.z, Z.w);
  float d0 = 1e10f, d1 = 1e10f, d2 = 1e10f, d3 = 1e10f;

  float cx = xs[0], cy = ys[0], cz = zs[0];     // first centroid = point 0

  // precompute publish addresses: lane r (<8) targets rank r's slot [par][myrank]
  uint32_t pub[2];
  if (wid == 0 && lane < CSZ){
    pub[0] = mapa_rank(smem_u32(&s_ex[0][rank]), (uint32_t)lane);
    pub[1] = mapa_rank(smem_u32(&s_ex[1][rank]), (uint32_t)lane);
  }

  for (int m = 0; m < NP; m++){
    // output writes on warp15 of rank0 — OFF the stage warp's (warp0) critical path
    if (rank == 0 && wid == NW-1 && lane == 0){
      const int bp = b*NP + m;
      newxyz[3*bp+0] = cx; newxyz[3*bp+1] = cy; newxyz[3*bp+2] = cz;
      g_qx[bp] = cx; g_qy[bp] = cy; g_qz[bp] = cz;
      g_qn[bp] = __fadd_rn(__fadd_rn(__fmul_rn(cx,cx), __fmul_rn(cy,cy)), __fmul_rn(cz,cz));
    }
    if (m == NP-1) break;

    // packed no-FMA distance update: (x-cx)^2+(y-cy)^2+(z-cz)^2 (reference rounding)
    {
      const unsigned long long ncx = pk2(-cx,-cx), ncy = pk2(-cy,-cy), ncz = pk2(-cz,-cz);
      const unsigned long long dxa = add2(PX0,ncx), dya = add2(PY0,ncy), dza = add2(PZ0,ncz);
      unsigned long long sa = mul2(dxa,dxa); sa = add2(sa, mul2(dya,dya)); sa = add2(sa, mul2(dza,dza));
      const unsigned long long dxb = add2(PX1,ncx), dyb = add2(PY1,ncy), dzb = add2(PZ1,ncz);
      unsigned long long sb = mul2(dxb,dxb); sb = add2(sb, mul2(dyb,dyb)); sb = add2(sb, mul2(dzb,dzb));
      float la, ha, lb, hb; upk2(sa, la, ha); upk2(sb, lb, hb);
      d0 = fminf(d0, la); d1 = fminf(d1, ha); d2 = fminf(d2, lb); d3 = fminf(d3, hb);
    }
    // thread-local argmax, first-index tie-break (strict >)
    float v = d0; int k = 0;
    if (d1 > v){ v = d1; k = 1; }
    if (d2 > v){ v = d2; k = 2; }
    if (d3 > v){ v = d3; k = 3; }
    const unsigned long long xp = (k&2)?PX1:PX0, yp = (k&2)?PY1:PY0, zp = (k&2)?PZ1:PZ0;
    float xl,xh,yl,yh,zl,zh; upk2(xp,xl,xh); upk2(yp,yl,yh); upk2(zp,zl,zh);
    const float bx=(k&1)?xh:xl, by=(k&1)?yh:yl, bz=(k&1)?zh:zl;
    // warp argmax: dists >= 0 so float bits order-isomorphic; lowest lane = lowest idx
    const unsigned vb   = __float_as_uint(v);
    const unsigned wmax = __reduce_max_sync(0xffffffffu, vb);
    const unsigned bal  = __ballot_sync(0xffffffffu, vb == wmax);
    if (lane == __ffs(bal)-1)
      s_c4[wid] = make_uint4(wmax, __float_as_uint(bx), __float_as_uint(by), __float_as_uint(bz));
    __syncthreads();

    const int par = m & 1;
    if (wid == 0){
      // block argmax over 16 warp candidates (lowest warp = lowest idx)
      const unsigned cv   = (lane < NW) ? s_c4[lane].x : 0u;
      const unsigned bmax = __reduce_max_sync(0xffffffffu, cv);
      const unsigned bal2 = __ballot_sync(0xffffffffu, cv == bmax);
      const uint4 w = s_c4[__ffs(bal2)-1];   // broadcast LDS of winner
      if (lane < CSZ)
        st_cl_v4(pub[par], w.x, w.y, w.z, w.w);
    }
    // HW cluster barrier: arrive(release) orders the publishes; wait(acquire)
    // makes all ranks' slots visible locally.
    cluster_sync_all();

    // tree combine of 8 rank candidates; right replaces left only on strict >,
    // left = lower rank at every level -> lowest rank wins ties (lowest index)
    {
      uint4 c0 = s_ex[par][0], c1 = s_ex[par][1], c2 = s_ex[par][2], c3 = s_ex[par][3];
      uint4 c4 = s_ex[par][4], c5 = s_ex[par][5], c6 = s_ex[par][6], c7 = s_ex[par][7];
      uint4 a0 = (c1.x > c0.x) ? c1 : c0;
      uint4 a1 = (c3.x > c2.x) ? c3 : c2;
      uint4 a2 = (c5.x > c4.x) ? c5 : c4;
      uint4 a3 = (c7.x > c6.x) ? c7 : c6;
      uint4 b0 = (a1.x > a0.x) ? a1 : a0;
      uint4 b1 = (a3.x > a2.x) ? a3 : a2;
      uint4 wn = (b1.x > b0.x) ? b1 : b0;
      cx = __uint_as_float(wn.y);
      cy = __uint_as_float(wn.z);
      cz = __uint_as_float(wn.w);
    }
  }
  cluster_sync_all();
}

// ---------------- ball query pass 1: two warps per (b,p), each scans half ----------------
__global__ __launch_bounds__(256) void bq_half_kernel(){
  const int gw   = (blockIdx.x*blockDim.x + threadIdx.x) >> 5;   // 0..16383
  const int lane = threadIdx.x & 31;
  const int pair = gw >> 1;            // (b,p) id 0..8191
  const int half = gw & 1;
  const int b = pair >> 10;
  const int base = half * HALF;
  const float* __restrict__ xs = g_xs + b*NPTS;
  const float* __restrict__ ys = g_ys + b*NPTS;
  const float* __restrict__ zs = g_zs + b*NPTS;
  const float* __restrict__ xn = g_xn + b*NPTS;
  const float qx = g_qx[pair], qy = g_qy[pair], qz = g_qz[pair], qn = g_qn[pair];
  int* __restrict__ o0 = g_o0h + gw*16;
  int* __restrict__ o1 = g_o1h + gw*32;
  int cnt0=0, cnt1=0;
  const unsigned lmask = (1u << lane) - 1u;

  for (int n0=base; n0<base+HALF; n0+=64){
    const int na = n0 + lane, nb2 = n0 + 32 + lane;
    const float xa = xs[na],  ya = ys[na],  za = zs[na],  pa = xn[na];
    const float xb = xs[nb2], yb = ys[nb2], zb = zs[nb2], pb = xn[nb2];
    const float dota = fmaf(qx,xa, fmaf(qy,ya, qz*za));
    const float dotb = fmaf(qx,xb, fmaf(qy,yb, qz*zb));
    const float d2a  = __fadd_rn(__fadd_rn(qn, pa), -2.f*dota);
    const float d2b  = __fadd_rn(__fadd_rn(qn, pb), -2.f*dotb);

    {
      const bool h0 = d2a < 0.25f, h1 = d2a < 1.0f;
      const unsigned m0 = __ballot_sync(0xffffffffu, h0);
      const unsigned m1 = __ballot_sync(0xffffffffu, h1);
      if (cnt0 < 16 && m0){
        const int r = __popc(m0 & lmask);
        if (h0 && cnt0 + r < 16) o0[cnt0 + r] = na;
        cnt0 = min(16, cnt0 + __popc(m0));
      }
      if (cnt1 < 32 && m1){
        const int r = __popc(m1 & lmask);
        if (h1 && cnt1 + r < 32) o1[cnt1 + r] = na;
        cnt1 = min(32, cnt1 + __popc(m1));
      }
    }
    {
      const bool h0 = d2b < 0.25f, h1 = d2b < 1.0f;
      const unsigned m0 = __ballot_sync(0xffffffffu, h0);
      const unsigned m1 = __ballot_sync(0xffffffffu, h1);
      if (cnt0 < 16 && m0){
        const int r = __popc(m0 & lmask);
        if (h0 && cnt0 + r < 16) o0[cnt0 + r] = nb2;
        cnt0 = min(16, cnt0 + __popc(m0));
      }
      if (cnt1 < 32 && m1){
        const int r = __popc(m1 & lmask);
        if (h1 && cnt1 + r < 32) o1[cnt1 + r] = nb2;
        cnt1 = min(32, cnt1 + __popc(m1));
      }
    }
    if (cnt0 >= 16 && cnt1 >= 32) break;
  }
  if (lane == 0){ g_c0h[gw] = cnt0; g_c1h[gw] = cnt1; }
}

// ---------------- ball query pass 2: merge halves (concatenation = index order) ----------------
__global__ __launch_bounds__(256) void bq_merge_kernel(){
  const int pair = (blockIdx.x*blockDim.x + threadIdx.x) >> 5;   // 0..8191
  const int lane = threadIdx.x & 31;
  const int wA = 2*pair, wB = 2*pair + 1;
  const int cA0 = g_c0h[wA], cB0 = g_c0h[wB];
  const int cA1 = g_c1h[wA], cB1 = g_c1h[wB];
  const int* __restrict__ A0 = g_o0h + wA*16;
  const int* __restrict__ B0 = g_o0h + wB*16;
  const int* __restrict__ A1 = g_o1h + wA*32;
  const int* __restrict__ B1 = g_o1h + wB*32;

  if (lane < 16){
    const int pad0 = (cA0 > 0) ? A0[0] : ((cB0 > 0) ? B0[0] : 0);
    int v;
    if (lane < cA0)            v = A0[lane];
    else if (lane < cA0 + cB0) v = B0[lane - cA0];
    else                       v = pad0;
    g_idx0[pair*16 + lane] = v;
  }
  {
    const int pad1 = (cA1 > 0) ? A1[0] : ((cB1 > 0) ? B1[0] : 0);
    int v;
    if (lane < cA1)            v = A1[lane];
    else if (lane < cA1 + cB1) v = B1[lane - cA1];
    else                       v = pad1;
    g_idx1[pair*32 + lane] = v;
  }
}

// ---------------- fused group + 2-layer MLP + maxpool (device body) ----------------
template<int S, int C1O, int C2O, int COFF>
__device__ __forceinline__ void mlp_body(
    int bp, char* smraw,
    const float* __restrict__ feats,
    const float* __restrict__ s1, const float* __restrict__ b1,
    const float* __restrict__ w2, const float* __restrict__ s2, const float* __restrict__ b2,
    float* __restrict__ outf)
{
  const int b = bp >> 10, p = bp & (NP-1);
  const int t = threadIdx.x;
  float* xin = (float*)smraw;            // 36*S
  float* h1s = xin + 36*S;               // C1O*S
  int*   sidx= (int*)(h1s + C1O*S);      // S
  float* red = (float*)(sidx + S);       // 128

  const int*   __restrict__ idxb = (COFF==0) ? g_idx0 : g_idx1;
  const float* __restrict__ w1p  = (COFF==0) ? g_w0p  : g_w1p;

  if (t < S) sidx[t] = idxb[bp*S + t];
  const float cx = g_qx[bp], cy = g_qy[bp], cz = g_qz[bp];
  const float* __restrict__ xsb = g_xs + b*NPTS;
  const float* __restrict__ ysb = g_ys + b*NPTS;
  const float* __restrict__ zsb = g_zs + b*NPTS;
  const float* __restrict__ fb  = feats + b*CIN*NPTS;
  __syncthreads();

  for (int e=t; e<35*S; e+=128){
    const int c = e / S, s = e - c*S;
    const int n = sidx[s];
    float v;
    if      (c==0) v = xsb[n]-cx;
    else if (c==1) v = ysb[n]-cy;
    else if (c==2) v = zsb[n]-cz;
    else           v = fb[(c-3)*NPTS + n];
    xin[c*S+s] = v;
  }
  if (t < S) xin[35*S+t] = 0.f;
  __syncthreads();

  // ---- layer 1: 35->C1O with packed f32x2 FMA (bit-exact vs scalar fmaf)
  constexpr int SPT1  = C1O*S/128;
  constexpr int NAC1  = SPT1/2;
  constexpr int G1    = S/SPT1;
  {
    const int o  = t / G1;
    const int sb = (t - o*G1)*SPT1;
    unsigned long long acc[NAC1];
#pragma unroll
    for (int i=0;i<NAC1;i++) acc[i]=0ull;
    const float* wr = w1p + o*36;
#pragma unroll 3
    for (int in=0; in<36; in+=4){
      const float4 w4 = *reinterpret_cast<const float4*>(wr+in);
      const float wv[4] = {w4.x,w4.y,w4.z,w4.w};
#pragma unroll
      for (int j=0;j<4;j++){
        const unsigned long long w2v = pk2(wv[j], wv[j]);
        const unsigned long long* xp =
          reinterpret_cast<const unsigned long long*>(&xin[(in+j)*S + sb]);
#pragma unroll
        for (int q=0;q<NAC1;q++) acc[q] = fma2(w2v, xp[q], acc[q]);
      }
    }
    const float sc = s1[o], bb = b1[o];
#pragma unroll
    for (int q=0;q<NAC1;q++){
      float a0, a1; upk2(acc[q], a0, a1);
      h1s[o*S + sb + 2*q    ] = fmaxf(fmaf(a0,sc,bb), 0.f);
      h1s[o*S + sb + 2*q + 1] = fmaxf(fmaf(a1,sc,bb), 0.f);
    }
  }
  __syncthreads();

  // ---- layer 2: C1O->C2O + ReLU + maxpool over S (packed f32x2 FMA)
  constexpr int SPT2 = C2O*S/128;
  constexpr int NAC2 = SPT2/2;
  constexpr int G2   = S/SPT2;
  {
    const int o  = t / G2;
    const int sb = (t - o*G2)*SPT2;
    unsigned long long acc[NAC2];
#pragma unroll
    for (int i=0;i<NAC2;i++) acc[i]=0ull;
    const float* wr = w2 + o*C1O;
#pragma unroll 4
    for (int in=0; in<C1O; in+=4){
      const float4 w4 = *reinterpret_cast<const float4*>(wr+in);
      const float wv[4] = {w4.x,w4.y,w4.z,w4.w};
#pragma unroll
      for (int j=0;j<4;j++){
        const unsigned long long w2v = pk2(wv[j], wv[j]);
        const unsigned long long* xp =
          reinterpret_cast<const unsigned long long*>(&h1s[(in+j)*S + sb]);
#pragma unroll
        for (int q=0;q<NAC2;q++) acc[q] = fma2(w2v, xp[q], acc[q]);
      }
    }
    const float sc = s2[o], bb = b2[o];
    float vm = 0.f;   // ReLU => max over relu == max(0, max(pre))
#pragma unroll
    for (int q=0;q<NAC2;q++){
      float a0, a1; upk2(acc[q], a0, a1);
      vm = fmaxf(vm, fmaf(a0,sc,bb));
      vm = fmaxf(vm, fmaf(a1,sc,bb));
    }
    if (G2 == 1){
      outf[(b*192 + COFF + o)*NP + p] = vm;
    } else {
      red[t] = vm;
      __syncthreads();
      if (t < C2O)
        outf[(b*192 + COFF + t)*NP + p] = fmaxf(red[t*G2], red[t*G2+1]);
    }
  }
}

// ---------------- merged MLP launch: both branches in one grid (overlap) ----------------
__global__ __launch_bounds__(128) void mlp_merged(
    const float* __restrict__ feats,
    const float* __restrict__ s00, const float* __restrict__ b00,
    const float* __restrict__ w01, const float* __restrict__ s01, const float* __restrict__ b01,
    const float* __restrict__ s10, const float* __restrict__ b10,
    const float* __restrict__ w11, const float* __restrict__ s11, const float* __restrict__ b11,
    float* __restrict__ outf)
{
  extern __shared__ char smraw[];
  if (blockIdx.x < NB*NP)
    mlp_body<16,32, 64, 0>(blockIdx.x,          smraw, feats, s00,b00, w01,s01,b01, outf);
  else
    mlp_body<32,64,128,64>(blockIdx.x - NB*NP,  smraw, feats, s10,b10, w11,s11,b11, outf);
}

#define MLP_SMEM ((36*32 + 64*32)*4 + 32*4 + 128*4)

// ---------------- launch ----------------
extern "C" void kernel_launch(void* const* d_in, const int* in_sizes, int n_in,
                              void* d_out, int out_size) {
  const float* xyz   = (const float*)d_in[0];
  const float* feats = (const float*)d_in[1];
  const float* w00 = (const float*)d_in[2];
  const float* s00 = (const float*)d_in[3];
  const float* b00 = (const float*)d_in[4];
  const float* w01 = (const float*)d_in[5];
  const float* s01 = (const float*)d_in[6];
  const float* b01 = (const float*)d_in[7];
  const float* w10 = (const float*)d_in[8];
  const float* s10 = (const float*)d_in[9];
  const float* b10 = (const float*)d_in[10];
  const float* w11 = (const float*)d_in[11];
  const float* s11 = (const float*)d_in[12];
  const float* b11 = (const float*)d_in[13];
  float* out = (float*)d_out;

  prep_soa<<<(NB*NPTS+255)/256, 256>>>(xyz);
  prep_w<<<1,256>>>(w00, w10);
  fps_kernel<<<NB*CSZ, FTH>>>(out);                    // writes new_xyz (B,P,3) at out[0..24575]
  bq_half_kernel<<<(2*NB*NP)/8, 256>>>();              // 16384 warps: 2 halves per center
  bq_merge_kernel<<<(NB*NP)/8, 256>>>();               // concatenate halves
  float* outf = out + NB*NP*3;                         // features (B,192,P)
  mlp_merged<<<2*NB*NP, 128, MLP_SMEM>>>(feats, s00,b00, w01,s01,b01,
                                         s10,b10, w11,s11,b11, outf);
}

// round 16
// speedup vs baseline: 1.0035x; 1.0035x over previous
#include <cuda_runtime.h>
#include <cstdint>

#define NPTS 16384
#define NB   8
#define NP   1024
#define CIN  32
#define CSZ  8                 // FPS cluster size (CTAs per batch)
#define SLICE (NPTS/CSZ)       // 2048 points per CTA
#define FTH  512               // FPS threads per CTA
#define PPT  (SLICE/FTH)       // 4 points per thread
#define NW   (FTH/32)          // 16 warps

// ---------------- scratch (static __device__, no allocation) ----------------
__device__ float g_xs[NB*NPTS], g_ys[NB*NPTS], g_zs[NB*NPTS], g_xn[NB*NPTS];
__device__ float g_qx[NB*NP], g_qy[NB*NP], g_qz[NB*NP], g_qn[NB*NP];
__device__ int   g_idx0[NB*NP*16];
__device__ int   g_idx1[NB*NP*32];
__device__ float g_w0p[32*36];   // branch0 L1 weights padded 35->36
__device__ float g_w1p[64*36];   // branch1 L1 weights padded 35->36

// ---------------- packed f32x2 helpers (Blackwell) ----------------
__device__ __forceinline__ unsigned long long pk2(float a, float b){
  unsigned long long r; asm("mov.b64 %0,{%1,%2};" : "=l"(r) : "f"(a), "f"(b)); return r;
}
__device__ __forceinline__ void upk2(unsigned long long v, float& a, float& b){
  asm("mov.b64 {%0,%1},%2;" : "=f"(a), "=f"(b) : "l"(v));
}
__device__ __forceinline__ unsigned long long add2(unsigned long long a, unsigned long long b){
  unsigned long long r; asm("add.rn.f32x2 %0,%1,%2;" : "=l"(r) : "l"(a), "l"(b)); return r;
}
__device__ __forceinline__ unsigned long long mul2(unsigned long long a, unsigned long long b){
  unsigned long long r; asm("mul.rn.f32x2 %0,%1,%2;" : "=l"(r) : "l"(a), "l"(b)); return r;
}
__device__ __forceinline__ unsigned long long fma2(unsigned long long a, unsigned long long b,
                                                  unsigned long long c){
  unsigned long long r; asm("fma.rn.f32x2 %0,%1,%2,%3;" : "=l"(r) : "l"(a), "l"(b), "l"(c));
  return r;
}

// ---------------- cluster / smem helpers ----------------
__device__ __forceinline__ uint32_t smem_u32(const void* p){
  return (uint32_t)__cvta_generic_to_shared(p);
}
__device__ __forceinline__ uint32_t mapa_rank(uint32_t laddr, uint32_t rank){
  uint32_t r; asm("mapa.shared::cluster.u32 %0, %1, %2;" : "=r"(r) : "r"(laddr), "r"(rank));
  return r;
}
__device__ __forceinline__ void st_cl_v4(uint32_t addr, unsigned a, unsigned b,
                                         unsigned c, unsigned d){
  asm volatile("st.shared::cluster.v4.b32 [%0],{%1,%2,%3,%4};"
               :: "r"(addr), "r"(a), "r"(b), "r"(c), "r"(d) : "memory");
}
__device__ __forceinline__ void cluster_sync_all(){
  asm volatile("barrier.cluster.arrive.aligned;" ::: "memory");
  asm volatile("barrier.cluster.wait.aligned;" ::: "memory");
}
__device__ __forceinline__ uint32_t ctarank(){
  uint32_t r; asm("mov.u32 %0, %%cluster_ctarank;" : "=r"(r)); return r;
}

// ---------------- prep: AoS->SoA + squared norms + weight padding ----------------
__global__ void prep_kernel(const float* __restrict__ xyz,
                            const float* __restrict__ w00,
                            const float* __restrict__ w10){
  const int i = blockIdx.x*blockDim.x + threadIdx.x;
  if (i < NB*NPTS){
    float x = xyz[3*i+0], y = xyz[3*i+1], z = xyz[3*i+2];
    g_xs[i]=x; g_ys[i]=y; g_zs[i]=z;
    g_xn[i] = __fadd_rn(__fadd_rn(__fmul_rn(x,x), __fmul_rn(y,y)), __fmul_rn(z,z));
  }
  if (blockIdx.x == 0){
    const int t = threadIdx.x;
    for (int e=t; e<32*36; e+=256){ int o=e/36, c=e-o*36; g_w0p[e] = (c<35) ? w00[o*35+c] : 0.f; }
    for (int e=t; e<64*36; e+=256){ int o=e/36, c=e-o*36; g_w1p[e] = (c<35) ? w10[o*35+c] : 0.f; }
  }
}

// ---------------- FPS: 8-CTA cluster, HW cluster-barrier exchange (R13/R14 winner) ----------------
__global__ void __cluster_dims__(CSZ,1,1) __launch_bounds__(FTH,1)
fps_kernel(float* __restrict__ newxyz){
  const int b = blockIdx.x / CSZ;
  const uint32_t rank = ctarank();
  const float* __restrict__ xs = g_xs + b*NPTS;
  const float* __restrict__ ys = g_ys + b*NPTS;
  const float* __restrict__ zs = g_zs + b*NPTS;
  const int t = threadIdx.x;
  const int lane = t & 31, wid = t >> 5;        // wid 0..15
  const int gi0 = rank*SLICE + t*PPT;           // 4 consecutive point indices

  __shared__ uint4 s_c4[NW];        // per-warp candidates {vb, x, y, z}
  __shared__ uint4 s_ex[2][CSZ];    // exchange slots [par][rank] {vb, x, y, z}

  // register-resident point coords (4 pts/thread)
  const float4 X = *reinterpret_cast<const float4*>(xs + gi0);
  const float4 Y = *reinterpret_cast<const float4*>(ys + gi0);
  const float4 Z = *reinterpret_cast<const float4*>(zs + gi0);
  const unsigned long long PX0 = pk2(X.x, X.y), PX1 = pk2(X.z, X.w);
  const unsigned long long PY0 = pk2(Y.x, Y.y), PY1 = pk2(Y.z, Y.w);
  const unsigned long long PZ0 = pk2(Z.x, Z.y), PZ1 = pk2(Z.z, Z.w);
  float d0 = 1e10f, d1 = 1e10f, d2 = 1e10f, d3 = 1e10f;

  float cx = xs[0], cy = ys[0], cz = zs[0];     // first centroid = point 0

  // precompute publish addresses: lane r (<8) targets rank r's slot [par][myrank]
  uint32_t pub[2];
  if (wid == 0 && lane < CSZ){
    pub[0] = mapa_rank(smem_u32(&s_ex[0][rank]), (uint32_t)lane);
    pub[1] = mapa_rank(smem_u32(&s_ex[1][rank]), (uint32_t)lane);
  }

  for (int m = 0; m < NP; m++){
    // output writes on warp15 of rank0 — OFF the stage warp's (warp0) critical path
    if (rank == 0 && wid == NW-1 && lane == 0){
      const int bp = b*NP + m;
      newxyz[3*bp+0] = cx; newxyz[3*bp+1] = cy; newxyz[3*bp+2] = cz;
      g_qx[bp] = cx; g_qy[bp] = cy; g_qz[bp] = cz;
      g_qn[bp] = __fadd_rn(__fadd_rn(__fmul_rn(cx,cx), __fmul_rn(cy,cy)), __fmul_rn(cz,cz));
    }
    if (m == NP-1) break;

    // packed no-FMA distance update: (x-cx)^2+(y-cy)^2+(z-cz)^2 (reference rounding)
    {
      const unsigned long long ncx = pk2(-cx,-cx), ncy = pk2(-cy,-cy), ncz = pk2(-cz,-cz);
      const unsigned long long dxa = add2(PX0,ncx), dya = add2(PY0,ncy), dza = add2(PZ0,ncz);
      unsigned long long sa = mul2(dxa,dxa); sa = add2(sa, mul2(dya,dya)); sa = add2(sa, mul2(dza,dza));
      const unsigned long long dxb = add2(PX1,ncx), dyb = add2(PY1,ncy), dzb = add2(PZ1,ncz);
      unsigned long long sb = mul2(dxb,dxb); sb = add2(sb, mul2(dyb,dyb)); sb = add2(sb, mul2(dzb,dzb));
      float la, ha, lb, hb; upk2(sa, la, ha); upk2(sb, lb, hb);
      d0 = fminf(d0, la); d1 = fminf(d1, ha); d2 = fminf(d2, lb); d3 = fminf(d3, hb);
    }
    // thread-local argmax, first-index tie-break (strict >)
    float v = d0; int k = 0;
    if (d1 > v){ v = d1; k = 1; }
    if (d2 > v){ v = d2; k = 2; }
    if (d3 > v){ v = d3; k = 3; }
    const unsigned long long xp = (k&2)?PX1:PX0, yp = (k&2)?PY1:PY0, zp = (k&2)?PZ1:PZ0;
    float xl,xh,yl,yh,zl,zh; upk2(xp,xl,xh); upk2(yp,yl,yh); upk2(zp,zl,zh);
    const float bx=(k&1)?xh:xl, by=(k&1)?yh:yl, bz=(k&1)?zh:zl;
    // warp argmax: dists >= 0 so float bits order-isomorphic; lowest lane = lowest idx
    const unsigned vb   = __float_as_uint(v);
    const unsigned wmax = __reduce_max_sync(0xffffffffu, vb);
    const unsigned bal  = __ballot_sync(0xffffffffu, vb == wmax);
    if (lane == __ffs(bal)-1)
      s_c4[wid] = make_uint4(wmax, __float_as_uint(bx), __float_as_uint(by), __float_as_uint(bz));
    __syncthreads();

    const int par = m & 1;
    if (wid == 0){
      // block argmax over 16 warp candidates (lowest warp = lowest idx)
      const unsigned cv   = (lane < NW) ? s_c4[lane].x : 0u;
      const unsigned bmax = __reduce_max_sync(0xffffffffu, cv);
      const unsigned bal2 = __ballot_sync(0xffffffffu, cv == bmax);
      const uint4 w = s_c4[__ffs(bal2)-1];   // broadcast LDS of winner
      if (lane < CSZ)
        st_cl_v4(pub[par], w.x, w.y, w.z, w.w);
    }
    // HW cluster barrier: arrive(release) orders the publishes; wait(acquire)
    // makes all ranks' slots visible locally.
    cluster_sync_all();

    // tree combine of 8 rank candidates; right replaces left only on strict >,
    // left = lower rank at every level -> lowest rank wins ties (lowest index)
    {
      uint4 c0 = s_ex[par][0], c1 = s_ex[par][1], c2 = s_ex[par][2], c3 = s_ex[par][3];
      uint4 c4 = s_ex[par][4], c5 = s_ex[par][5], c6 = s_ex[par][6], c7 = s_ex[par][7];
      uint4 a0 = (c1.x > c0.x) ? c1 : c0;
      uint4 a1 = (c3.x > c2.x) ? c3 : c2;
      uint4 a2 = (c5.x > c4.x) ? c5 : c4;
      uint4 a3 = (c7.x > c6.x) ? c7 : c6;
      uint4 b0 = (a1.x > a0.x) ? a1 : a0;
      uint4 b1 = (a3.x > a2.x) ? a3 : a2;
      uint4 wn = (b1.x > b0.x) ? b1 : b0;
      cx = __uint_as_float(wn.y);
      cy = __uint_as_float(wn.z);
      cz = __uint_as_float(wn.w);
    }
  }
  cluster_sync_all();
}

// ---------------- ball query: one warp per (b,p), 64-pt unrolled scan (R13 best) ----------------
__global__ __launch_bounds__(256) void ballquery_kernel(){
  const int warp = (blockIdx.x*blockDim.x + threadIdx.x) >> 5;   // 0..8191
  const int lane = threadIdx.x & 31;
  const int b = warp >> 10;
  const float* __restrict__ xs = g_xs + b*NPTS;
  const float* __restrict__ ys = g_ys + b*NPTS;
  const float* __restrict__ zs = g_zs + b*NPTS;
  const float* __restrict__ xn = g_xn + b*NPTS;
  const float qx = g_qx[warp], qy = g_qy[warp], qz = g_qz[warp], qn = g_qn[warp];
  int* __restrict__ o0 = g_idx0 + warp*16;
  int* __restrict__ o1 = g_idx1 + warp*32;
  int cnt0=0, cnt1=0, f0=0, f1=0;
  const unsigned lmask = (1u << lane) - 1u;

  for (int n0=0; n0<NPTS; n0+=64){
    const int na = n0 + lane, nb2 = n0 + 32 + lane;
    const float xa = xs[na],  ya = ys[na],  za = zs[na],  pa = xn[na];
    const float xb = xs[nb2], yb = ys[nb2], zb = zs[nb2], pb = xn[nb2];
    const float dota = fmaf(qx,xa, fmaf(qy,ya, qz*za));
    const float dotb = fmaf(qx,xb, fmaf(qy,yb, qz*zb));
    const float d2a  = __fadd_rn(__fadd_rn(qn, pa), -2.f*dota);
    const float d2b  = __fadd_rn(__fadd_rn(qn, pb), -2.f*dotb);

    {
      const bool h0 = d2a < 0.25f, h1 = d2a < 1.0f;
      const unsigned m0 = __ballot_sync(0xffffffffu, h0);
      const unsigned m1 = __ballot_sync(0xffffffffu, h1);
      if (cnt0 < 16 && m0){
        if (cnt0 == 0) f0 = n0 + __ffs(m0) - 1;
        const int r = __popc(m0 & lmask);
        if (h0 && cnt0 + r < 16) o0[cnt0 + r] = na;
        cnt0 = min(16, cnt0 + __popc(m0));
      }
      if (cnt1 < 32 && m1){
        if (cnt1 == 0) f1 = n0 + __ffs(m1) - 1;
        const int r = __popc(m1 & lmask);
        if (h1 && cnt1 + r < 32) o1[cnt1 + r] = na;
        cnt1 = min(32, cnt1 + __popc(m1));
      }
    }
    {
      const bool h0 = d2b < 0.25f, h1 = d2b < 1.0f;
      const unsigned m0 = __ballot_sync(0xffffffffu, h0);
      const unsigned m1 = __ballot_sync(0xffffffffu, h1);
      if (cnt0 < 16 && m0){
        if (cnt0 == 0) f0 = n0 + 32 + __ffs(m0) - 1;
        const int r = __popc(m0 & lmask);
        if (h0 && cnt0 + r < 16) o0[cnt0 + r] = nb2;
        cnt0 = min(16, cnt0 + __popc(m0));
      }
      if (cnt1 < 32 && m1){
        if (cnt1 == 0) f1 = n0 + 32 + __ffs(m1) - 1;
        const int r = __popc(m1 & lmask);
        if (h1 && cnt1 + r < 32) o1[cnt1 + r] = nb2;
        cnt1 = min(32, cnt1 + __popc(m1));
      }
    }
    if (cnt0 >= 16 && cnt1 >= 32) break;
  }
  if (lane >= cnt0 && lane < 16) o0[lane] = f0;   // pad with first hit (0 if none)
  if (lane >= cnt1)              o1[lane] = f1;
}

// ---------------- fused group + 2-layer MLP + maxpool (device body) ----------------
template<int S, int C1O, int C2O, int COFF>
__device__ __forceinline__ void mlp_body(
    int bp, char* smraw,
    const float* __restrict__ feats,
    const float* __restrict__ s1, const float* __restrict__ b1,
    const float* __restrict__ w2, const float* __restrict__ s2, const float* __restrict__ b2,
    float* __restrict__ outf)
{
  const int b = bp >> 10, p = bp & (NP-1);
  const int t = threadIdx.x;
  float* xin = (float*)smraw;            // 36*S
  float* h1s = xin + 36*S;               // C1O*S
  int*   sidx= (int*)(h1s + C1O*S);      // S
  float* red = (float*)(sidx + S);       // 128

  const int*   __restrict__ idxb = (COFF==0) ? g_idx0 : g_idx1;
  const float* __restrict__ w1p  = (COFF==0) ? g_w0p  : g_w1p;

  if (t < S) sidx[t] = idxb[bp*S + t];
  const float cx = g_qx[bp], cy = g_qy[bp], cz = g_qz[bp];
  const float* __restrict__ xsb = g_xs + b*NPTS;
  const float* __restrict__ ysb = g_ys + b*NPTS;
  const float* __restrict__ zsb = g_zs + b*NPTS;
  const float* __restrict__ fb  = feats + b*CIN*NPTS;
  __syncthreads();

  for (int e=t; e<35*S; e+=128){
    const int c = e / S, s = e - c*S;
    const int n = sidx[s];
    float v;
    if      (c==0) v = xsb[n]-cx;
    else if (c==1) v = ysb[n]-cy;
    else if (c==2) v = zsb[n]-cz;
    else           v = fb[(c-3)*NPTS + n];
    xin[c*S+s] = v;
  }
  if (t < S) xin[35*S+t] = 0.f;
  __syncthreads();

  // ---- layer 1: 35->C1O with packed f32x2 FMA (bit-exact vs scalar fmaf)
  constexpr int SPT1  = C1O*S/128;
  constexpr int NAC1  = SPT1/2;
  constexpr int G1    = S/SPT1;
  {
    const int o  = t / G1;
    const int sb = (t - o*G1)*SPT1;
    unsigned long long acc[NAC1];
#pragma unroll
    for (int i=0;i<NAC1;i++) acc[i]=0ull;
    const float* wr = w1p + o*36;
#pragma unroll 3
    for (int in=0; in<36; in+=4){
      const float4 w4 = *reinterpret_cast<const float4*>(wr+in);
      const float wv[4] = {w4.x,w4.y,w4.z,w4.w};
#pragma unroll
      for (int j=0;j<4;j++){
        const unsigned long long w2v = pk2(wv[j], wv[j]);
        const unsigned long long* xp =
          reinterpret_cast<const unsigned long long*>(&xin[(in+j)*S + sb]);
#pragma unroll
        for (int q=0;q<NAC1;q++) acc[q] = fma2(w2v, xp[q], acc[q]);
      }
    }
    const float sc = s1[o], bb = b1[o];
#pragma unroll
    for (int q=0;q<NAC1;q++){
      float a0, a1; upk2(acc[q], a0, a1);
      h1s[o*S + sb + 2*q    ] = fmaxf(fmaf(a0,sc,bb), 0.f);
      h1s[o*S + sb + 2*q + 1] = fmaxf(fmaf(a1,sc,bb), 0.f);
    }
  }
  __syncthreads();

  // ---- layer 2: C1O->C2O + ReLU + maxpool over S (packed f32x2 FMA)
  constexpr int SPT2 = C2O*S/128;
  constexpr int NAC2 = SPT2/2;
  constexpr int G2   = S/SPT2;
  {
    const int o  = t / G2;
    const int sb = (t - o*G2)*SPT2;
    unsigned long long acc[NAC2];
#pragma unroll
    for (int i=0;i<NAC2;i++) acc[i]=0ull;
    const float* wr = w2 + o*C1O;
#pragma unroll 4
    for (int in=0; in<C1O; in+=4){
      const float4 w4 = *reinterpret_cast<const float4*>(wr+in);
      const float wv[4] = {w4.x,w4.y,w4.z,w4.w};
#pragma unroll
      for (int j=0;j<4;j++){
        const unsigned long long w2v = pk2(wv[j], wv[j]);
        const unsigned long long* xp =
          reinterpret_cast<const unsigned long long*>(&h1s[(in+j)*S + sb]);
#pragma unroll
        for (int q=0;q<NAC2;q++) acc[q] = fma2(w2v, xp[q], acc[q]);
      }
    }
    const float sc = s2[o], bb = b2[o];
    float vm = 0.f;   // ReLU => max over relu == max(0, max(pre))
#pragma unroll
    for (int q=0;q<NAC2;q++){
      float a0, a1; upk2(acc[q], a0, a1);
      vm = fmaxf(vm, fmaf(a0,sc,bb));
      vm = fmaxf(vm, fmaf(a1,sc,bb));
    }
    if (G2 == 1){
      outf[(b*192 + COFF + o)*NP + p] = vm;
    } else {
      red[t] = vm;
      __syncthreads();
      if (t < C2O)
        outf[(b*192 + COFF + t)*NP + p] = fmaxf(red[t*G2], red[t*G2+1]);
    }
  }
}

// ---------------- merged MLP launch: both branches in one grid (overlap) ----------------
__global__ __launch_bounds__(128) void mlp_merged(
    const float* __restrict__ feats,
    const float* __restrict__ s00, const float* __restrict__ b00,
    const float* __restrict__ w01, const float* __restrict__ s01, const float* __restrict__ b01,
    const float* __restrict__ s10, const float* __restrict__ b10,
    const float* __restrict__ w11, const float* __restrict__ s11, const float* __restrict__ b11,
    float* __restrict__ outf)
{
  extern __shared__ char smraw[];
  if (blockIdx.x < NB*NP)
    mlp_body<16,32, 64, 0>(blockIdx.x,          smraw, feats, s00,b00, w01,s01,b01, outf);
  else
    mlp_body<32,64,128,64>(blockIdx.x - NB*NP,  smraw, feats, s10,b10, w11,s11,b11, outf);
}

#define MLP_SMEM ((36*32 + 64*32)*4 + 32*4 + 128*4)

// ---------------- launch ----------------
extern "C" void kernel_launch(void* const* d_in, const int* in_sizes, int n_in,
                              void* d_out, int out_size) {
  const float* xyz   = (const float*)d_in[0];
  const float* feats = (const float*)d_in[1];
  const float* w00 = (const float*)d_in[2];
  const float* s00 = (const float*)d_in[3];
  const float* b00 = (const float*)d_in[4];
  const float* w01 = (const float*)d_in[5];
  const float* s01 = (const float*)d_in[6];
  const float* b01 = (const float*)d_in[7];
  const float* w10 = (const float*)d_in[8];
  const float* s10 = (const float*)d_in[9];
  const float* b10 = (const float*)d_in[10];
  const float* w11 = (const float*)d_in[11];
  const float* s11 = (const float*)d_in[12];
  const float* b11 = (const float*)d_in[13];
  float* out = (float*)d_out;

  prep_kernel<<<(NB*NPTS+255)/256, 256>>>(xyz, w00, w10);
  fps_kernel<<<NB*CSZ, FTH>>>(out);                    // writes new_xyz (B,P,3) at out[0..24575]
  ballquery_kernel<<<(NB*NP)/8, 256>>>();
  float* outf = out + NB*NP*3;                         // features (B,192,P)
  mlp_merged<<<2*NB*NP, 128, MLP_SMEM>>>(feats, s00,b00, w01,s01,b01,
                                         s10,b10, w11,s11,b11, outf);
}

// round 17
// speedup vs baseline: 1.0897x; 1.0859x over previous
#include <cuda_runtime.h>
#include <cstdint>

#define NPTS 16384
#define NB   8
#define NP   1024
#define CIN  32
#define CSZ  8                 // FPS cluster size (CTAs per batch)
#define SLICE (NPTS/CSZ)       // 2048 points per CTA
#define FTH  512               // FPS threads per CTA
#define PPT  (SLICE/FTH)       // 4 points per thread
#define NW   (FTH/32)          // 16 warps

// ---------------- scratch (static __device__, no allocation) ----------------
__device__ float g_xs[NB*NPTS], g_ys[NB*NPTS], g_zs[NB*NPTS], g_xn[NB*NPTS];
__device__ float g_qx[NB*NP], g_qy[NB*NP], g_qz[NB*NP], g_qn[NB*NP];
__device__ int   g_idx0[NB*NP*16];
__device__ int   g_idx1[NB*NP*32];
// transposed weights: wt[c][o] so CB consecutive out-channels load as one vector
__device__ float g_w0t[36*32];    // b0 L1 (36 in x 32 out), row 35 zero
__device__ float g_w1t[36*64];    // b1 L1 (36 x 64), row 35 zero
__device__ float g_w0u[32*64];    // b0 L2 (32 in x 64 out)
__device__ float g_w1u[64*128];   // b1 L2 (64 x 128)

// ---------------- packed f32x2 helpers (Blackwell) ----------------
__device__ __forceinline__ unsigned long long pk2(float a, float b){
  unsigned long long r; asm("mov.b64 %0,{%1,%2};" : "=l"(r) : "f"(a), "f"(b)); return r;
}
__device__ __forceinline__ void upk2(unsigned long long v, float& a, float& b){
  asm("mov.b64 {%0,%1},%2;" : "=f"(a), "=f"(b) : "l"(v));
}
__device__ __forceinline__ unsigned long long add2(unsigned long long a, unsigned long long b){
  unsigned long long r; asm("add.rn.f32x2 %0,%1,%2;" : "=l"(r) : "l"(a), "l"(b)); return r;
}
__device__ __forceinline__ unsigned long long mul2(unsigned long long a, unsigned long long b){
  unsigned long long r; asm("mul.rn.f32x2 %0,%1,%2;" : "=l"(r) : "l"(a), "l"(b)); return r;
}
__device__ __forceinline__ unsigned long long fma2(unsigned long long a, unsigned long long b,
                                                  unsigned long long c){
  unsigned long long r; asm("fma.rn.f32x2 %0,%1,%2,%3;" : "=l"(r) : "l"(a), "l"(b), "l"(c));
  return r;
}

// ---------------- cluster / smem helpers ----------------
__device__ __forceinline__ uint32_t smem_u32(const void* p){
  return (uint32_t)__cvta_generic_to_shared(p);
}
__device__ __forceinline__ uint32_t mapa_rank(uint32_t laddr, uint32_t rank){
  uint32_t r; asm("mapa.shared::cluster.u32 %0, %1, %2;" : "=r"(r) : "r"(laddr), "r"(rank));
  return r;
}
__device__ __forceinline__ void st_cl_v4(uint32_t addr, unsigned a, unsigned b,
                                         unsigned c, unsigned d){
  asm volatile("st.shared::cluster.v4.b32 [%0],{%1,%2,%3,%4};"
               :: "r"(addr), "r"(a), "r"(b), "r"(c), "r"(d) : "memory");
}
__device__ __forceinline__ void cluster_sync_all(){
  asm volatile("barrier.cluster.arrive.aligned;" ::: "memory");
  asm volatile("barrier.cluster.wait.aligned;" ::: "memory");
}
__device__ __forceinline__ uint32_t ctarank(){
  uint32_t r; asm("mov.u32 %0, %%cluster_ctarank;" : "=r"(r)); return r;
}

// ---------------- prep: SoA + norms + transposed weights ----------------
__global__ void prep_kernel(const float* __restrict__ xyz,
                            const float* __restrict__ w00, const float* __restrict__ w01,
                            const float* __restrict__ w10, const float* __restrict__ w11){
  const int i = blockIdx.x*blockDim.x + threadIdx.x;
  if (i < NB*NPTS){
    float x = xyz[3*i+0], y = xyz[3*i+1], z = xyz[3*i+2];
    g_xs[i]=x; g_ys[i]=y; g_zs[i]=z;
    g_xn[i] = __fadd_rn(__fadd_rn(__fmul_rn(x,x), __fmul_rn(y,y)), __fmul_rn(z,z));
  }
  if (blockIdx.x == 0){
    const int t = threadIdx.x;
    for (int e=t; e<36*32;  e+=256){ int c=e>>5,  o=e&31;  g_w0t[e] = (c<35) ? w00[o*35+c] : 0.f; }
    for (int e=t; e<36*64;  e+=256){ int c=e/64,  o=e-64*c;  g_w1t[e] = (c<35) ? w10[o*35+c] : 0.f; }
    for (int e=t; e<32*64;  e+=256){ int c=e>>6,  o=e&63;  g_w0u[e] = w01[o*32+c]; }
    for (int e=t; e<64*128; e+=256){ int c=e>>7,  o=e&127; g_w1u[e] = w11[o*64+c]; }
  }
}

// ---------------- FPS: 8-CTA cluster, HW cluster-barrier exchange (exact R13 winner) ----------------
__global__ void __cluster_dims__(CSZ,1,1) __launch_bounds__(FTH,1)
fps_kernel(float* __restrict__ newxyz){
  const int b = blockIdx.x / CSZ;
  const uint32_t rank = ctarank();
  const float* __restrict__ xs = g_xs + b*NPTS;
  const float* __restrict__ ys = g_ys + b*NPTS;
  const float* __restrict__ zs = g_zs + b*NPTS;
  const int t = threadIdx.x;
  const int lane = t & 31, wid = t >> 5;        // wid 0..15
  const int gi0 = rank*SLICE + t*PPT;           // 4 consecutive point indices

  __shared__ uint4 s_c4[NW];        // per-warp candidates {vb, x, y, z}
  __shared__ uint4 s_ex[2][CSZ];    // exchange slots [par][rank] {vb, x, y, z}

  const float4 X = *reinterpret_cast<const float4*>(xs + gi0);
  const float4 Y = *reinterpret_cast<const float4*>(ys + gi0);
  const float4 Z = *reinterpret_cast<const float4*>(zs + gi0);
  const unsigned long long PX0 = pk2(X.x, X.y), PX1 = pk2(X.z, X.w);
  const unsigned long long PY0 = pk2(Y.x, Y.y), PY1 = pk2(Y.z, Y.w);
  const unsigned long long PZ0 = pk2(Z.x, Z.y), PZ1 = pk2(Z.z, Z.w);
  float d0 = 1e10f, d1 = 1e10f, d2 = 1e10f, d3 = 1e10f;

  float cx = xs[0], cy = ys[0], cz = zs[0];     // first centroid = point 0

  uint32_t pub[2];
  if (wid == 0 && lane < CSZ){
    pub[0] = mapa_rank(smem_u32(&s_ex[0][rank]), (uint32_t)lane);
    pub[1] = mapa_rank(smem_u32(&s_ex[1][rank]), (uint32_t)lane);
  }

  for (int m = 0; m < NP; m++){
    if (rank == 0 && t == 0){
      const int bp = b*NP + m;
      newxyz[3*bp+0] = cx; newxyz[3*bp+1] = cy; newxyz[3*bp+2] = cz;
      g_qx[bp] = cx; g_qy[bp] = cy; g_qz[bp] = cz;
      g_qn[bp] = __fadd_rn(__fadd_rn(__fmul_rn(cx,cx), __fmul_rn(cy,cy)), __fmul_rn(cz,cz));
    }
    if (m == NP-1) break;

    // packed no-FMA distance update (reference rounding)
    {
      const unsigned long long ncx = pk2(-cx,-cx), ncy = pk2(-cy,-cy), ncz = pk2(-cz,-cz);
      const unsigned long long dxa = add2(PX0,ncx), dya = add2(PY0,ncy), dza = add2(PZ0,ncz);
      unsigned long long sa = mul2(dxa,dxa); sa = add2(sa, mul2(dya,dya)); sa = add2(sa, mul2(dza,dza));
      const unsigned long long dxb = add2(PX1,ncx), dyb = add2(PY1,ncy), dzb = add2(PZ1,ncz);
      unsigned long long sb = mul2(dxb,dxb); sb = add2(sb, mul2(dyb,dyb)); sb = add2(sb, mul2(dzb,dzb));
      float la, ha, lb, hb; upk2(sa, la, ha); upk2(sb, lb, hb);
      d0 = fminf(d0, la); d1 = fminf(d1, ha); d2 = fminf(d2, lb); d3 = fminf(d3, hb);
    }
    // thread-local argmax, first-index tie-break (strict >)
    float v = d0; int k = 0;
    if (d1 > v){ v = d1; k = 1; }
    if (d2 > v){ v = d2; k = 2; }
    if (d3 > v){ v = d3; k = 3; }
    const unsigned long long xp = (k&2)?PX1:PX0, yp = (k&2)?PY1:PY0, zp = (k&2)?PZ1:PZ0;
    float xl,xh,yl,yh,zl,zh; upk2(xp,xl,xh); upk2(yp,yl,yh); upk2(zp,zl,zh);
    const float bx=(k&1)?xh:xl, by=(k&1)?yh:yl, bz=(k&1)?zh:zl;
    const unsigned vb   = __float_as_uint(v);
    const unsigned wmax = __reduce_max_sync(0xffffffffu, vb);
    const unsigned bal  = __ballot_sync(0xffffffffu, vb == wmax);
    if (lane == __ffs(bal)-1)
      s_c4[wid] = make_uint4(wmax, __float_as_uint(bx), __float_as_uint(by), __float_as_uint(bz));
    __syncthreads();

    const int par = m & 1;
    if (wid == 0){
      const unsigned cv   = (lane < NW) ? s_c4[lane].x : 0u;
      const unsigned bmax = __reduce_max_sync(0xffffffffu, cv);
      const unsigned bal2 = __ballot_sync(0xffffffffu, cv == bmax);
      const uint4 w = s_c4[__ffs(bal2)-1];
      if (lane < CSZ)
        st_cl_v4(pub[par], w.x, w.y, w.z, w.w);
    }
    cluster_sync_all();

    // combine 8 rank candidates; strict > keeps lowest rank = lowest idx
    uint4 best = s_ex[par][0];
#pragma unroll
    for (int r = 1; r < CSZ; r++){
      const uint4 c = s_ex[par][r];
      if (c.x > best.x) best = c;
    }
    cx = __uint_as_float(best.y);
    cy = __uint_as_float(best.z);
    cz = __uint_as_float(best.w);
  }
  cluster_sync_all();
}

// ---------------- ball query: one warp per (b,p), 64-pt unrolled scan (R13 best) ----------------
__global__ __launch_bounds__(256) void ballquery_kernel(){
  const int warp = (blockIdx.x*blockDim.x + threadIdx.x) >> 5;   // 0..8191
  const int lane = threadIdx.x & 31;
  const int b = warp >> 10;
  const float* __restrict__ xs = g_xs + b*NPTS;
  const float* __restrict__ ys = g_ys + b*NPTS;
  const float* __restrict__ zs = g_zs + b*NPTS;
  const float* __restrict__ xn = g_xn + b*NPTS;
  const float qx = g_qx[warp], qy = g_qy[warp], qz = g_qz[warp], qn = g_qn[warp];
  int* __restrict__ o0 = g_idx0 + warp*16;
  int* __restrict__ o1 = g_idx1 + warp*32;
  int cnt0=0, cnt1=0, f0=0, f1=0;
  const unsigned lmask = (1u << lane) - 1u;

  for (int n0=0; n0<NPTS; n0+=64){
    const int na = n0 + lane, nb2 = n0 + 32 + lane;
    const float xa = xs[na],  ya = ys[na],  za = zs[na],  pa = xn[na];
    const float xb = xs[nb2], yb = ys[nb2], zb = zs[nb2], pb = xn[nb2];
    const float dota = fmaf(qx,xa, fmaf(qy,ya, qz*za));
    const float dotb = fmaf(qx,xb, fmaf(qy,yb, qz*zb));
    const float d2a  = __fadd_rn(__fadd_rn(qn, pa), -2.f*dota);
    const float d2b  = __fadd_rn(__fadd_rn(qn, pb), -2.f*dotb);

    {
      const bool h0 = d2a < 0.25f, h1 = d2a < 1.0f;
      const unsigned m0 = __ballot_sync(0xffffffffu, h0);
      const unsigned m1 = __ballot_sync(0xffffffffu, h1);
      if (cnt0 < 16 && m0){
        if (cnt0 == 0) f0 = n0 + __ffs(m0) - 1;
        const int r = __popc(m0 & lmask);
        if (h0 && cnt0 + r < 16) o0[cnt0 + r] = na;
        cnt0 = min(16, cnt0 + __popc(m0));
      }
      if (cnt1 < 32 && m1){
        if (cnt1 == 0) f1 = n0 + __ffs(m1) - 1;
        const int r = __popc(m1 & lmask);
        if (h1 && cnt1 + r < 32) o1[cnt1 + r] = na;
        cnt1 = min(32, cnt1 + __popc(m1));
      }
    }
    {
      const bool h0 = d2b < 0.25f, h1 = d2b < 1.0f;
      const unsigned m0 = __ballot_sync(0xffffffffu, h0);
      const unsigned m1 = __ballot_sync(0xffffffffu, h1);
      if (cnt0 < 16 && m0){
        if (cnt0 == 0) f0 = n0 + 32 + __ffs(m0) - 1;
        const int r = __popc(m0 & lmask);
        if (h0 && cnt0 + r < 16) o0[cnt0 + r] = nb2;
        cnt0 = min(16, cnt0 + __popc(m0));
      }
      if (cnt1 < 32 && m1){
        if (cnt1 == 0) f1 = n0 + 32 + __ffs(m1) - 1;
        const int r = __popc(m1 & lmask);
        if (h1 && cnt1 + r < 32) o1[cnt1 + r] = nb2;
        cnt1 = min(32, cnt1 + __popc(m1));
      }
    }
    if (cnt0 >= 16 && cnt1 >= 32) break;
  }
  if (lane >= cnt0 && lane < 16) o0[lane] = f0;   // pad with first hit (0 if none)
  if (lane >= cnt1)              o1[lane] = f1;
}

// ---------------- register-blocked fused MLP body ----------------
// Each thread computes a CB-channel x SB-sample tile: one activation load feeds
// CB accumulators (4x less LDS traffic than 1-channel-per-thread). Weights come
// from transposed layouts wt[c][o] (CB consecutive outs = one vector load,
// contiguous across a warp). Accumulation order over input channels c ascending
// is IDENTICAL to previous rounds -> bit-exact results; maxpool re-association
// is exact (fmax on finite floats).
template<int S, int C1O, int C2O, int COFF, int CB1, int SB1, int SB2>
__device__ __forceinline__ void mlp_body(
    int bp, char* smraw,
    const float* __restrict__ feats,
    const float* __restrict__ wt1, const float* __restrict__ s1, const float* __restrict__ b1,
    const float* __restrict__ wt2, const float* __restrict__ s2, const float* __restrict__ b2,
    float* __restrict__ outf)
{
  const int b = bp >> 10, p = bp & (NP-1);
  const int t = threadIdx.x;
  float* xin = (float*)smraw;            // 36*S
  float* h1s = xin + 36*S;               // C1O*S
  int*   sidx= (int*)(h1s + C1O*S);      // S
  float* red = (float*)(sidx + S);       // 128*4

  const int* __restrict__ idxb = (COFF==0) ? g_idx0 : g_idx1;

  if (t < S) sidx[t] = idxb[bp*S + t];
  const float cx = g_qx[bp], cy = g_qy[bp], cz = g_qz[bp];
  const float* __restrict__ xsb = g_xs + b*NPTS;
  const float* __restrict__ ysb = g_ys + b*NPTS;
  const float* __restrict__ zsb = g_zs + b*NPTS;
  const float* __restrict__ fb  = feats + b*CIN*NPTS;
  __syncthreads();

  for (int e=t; e<35*S; e+=128){
    const int c = e / S, s = e - c*S;
    const int n = sidx[s];
    float v;
    if      (c==0) v = xsb[n]-cx;
    else if (c==1) v = ysb[n]-cy;
    else if (c==2) v = zsb[n]-cz;
    else           v = fb[(c-3)*NPTS + n];
    xin[c*S+s] = v;
  }
  if (t < S) xin[35*S+t] = 0.f;
  __syncthreads();

  // ---- layer 1: 36->C1O, CB1 channels x SB1 samples per thread
  {
    constexpr int NSG = S / SB1;          // sample groups
    constexpr int NP2 = SB1 / 2;          // packed pairs
    const int ob = t / NSG;               // channel-block index
    const int sb = (t - ob*NSG) * SB1;
    unsigned long long acc[CB1][NP2];
#pragma unroll
    for (int i=0;i<CB1;i++)
#pragma unroll
      for (int pp=0;pp<NP2;pp++) acc[i][pp]=0ull;

#pragma unroll 4
    for (int c = 0; c < 36; c++){
      float wv[CB1];
      if constexpr (CB1 == 4){
        const float4 w4 = *reinterpret_cast<const float4*>(wt1 + c*C1O + ob*4);
        wv[0]=w4.x; wv[1]=w4.y; wv[2]=w4.z; wv[3]=w4.w;
      } else {
        const float2 w2_ = *reinterpret_cast<const float2*>(wt1 + c*C1O + ob*2);
        wv[0]=w2_.x; wv[1]=w2_.y;
      }
      const unsigned long long* xp =
        reinterpret_cast<const unsigned long long*>(&xin[c*S + sb]);
#pragma unroll
      for (int pp=0; pp<NP2; pp++){
        const unsigned long long xv = xp[pp];
#pragma unroll
        for (int i=0;i<CB1;i++)
          acc[i][pp] = fma2(pk2(wv[i],wv[i]), xv, acc[i][pp]);
      }
    }
#pragma unroll
    for (int i=0;i<CB1;i++){
      const int o = ob*CB1 + i;
      const float sc = s1[o], bb = b1[o];
#pragma unroll
      for (int pp=0;pp<NP2;pp++){
        float a0, a1; upk2(acc[i][pp], a0, a1);
        h1s[o*S + sb + 2*pp    ] = fmaxf(fmaf(a0,sc,bb), 0.f);
        h1s[o*S + sb + 2*pp + 1] = fmaxf(fmaf(a1,sc,bb), 0.f);
      }
    }
  }
  __syncthreads();

  // ---- layer 2: C1O->C2O, 4 channels x SB2 samples per thread + maxpool
  {
    constexpr int NSG = S / SB2;
    constexpr int NP2 = SB2 / 2;
    const int ob = t / NSG;
    const int sb = (t - ob*NSG) * SB2;
    unsigned long long acc[4][NP2];
#pragma unroll
    for (int i=0;i<4;i++)
#pragma unroll
      for (int pp=0;pp<NP2;pp++) acc[i][pp]=0ull;

#pragma unroll 4
    for (int c = 0; c < C1O; c++){
      const float4 w4 = *reinterpret_cast<const float4*>(wt2 + c*C2O + ob*4);
      const float wv[4] = {w4.x, w4.y, w4.z, w4.w};
      const unsigned long long* xp =
        reinterpret_cast<const unsigned long long*>(&h1s[c*S + sb]);
#pragma unroll
      for (int pp=0; pp<NP2; pp++){
        const unsigned long long xv = xp[pp];
#pragma unroll
        for (int i=0;i<4;i++)
          acc[i][pp] = fma2(pk2(wv[i],wv[i]), xv, acc[i][pp]);
      }
    }
    // per-thread channel maxes (ReLU folded: max(0, ...))
#pragma unroll
    for (int i=0;i<4;i++){
      const int o = ob*4 + i;
      const float sc = s2[o], bb = b2[o];
      float vm = 0.f;
#pragma unroll
      for (int pp=0;pp<NP2;pp++){
        float a0, a1; upk2(acc[i][pp], a0, a1);
        vm = fmaxf(vm, fmaf(a0,sc,bb));
        vm = fmaxf(vm, fmaf(a1,sc,bb));
      }
      red[t*4 + i] = vm;
    }
    __syncthreads();
    if (t < C2O){
      const int o = t, ob2 = o >> 2, ci = o & 3;
      float v = red[(ob2*NSG + 0)*4 + ci];
#pragma unroll
      for (int sg = 1; sg < NSG; sg++)
        v = fmaxf(v, red[(ob2*NSG + sg)*4 + ci]);
      outf[(b*192 + COFF + o)*NP + p] = v;
    }
  }
}

// ---------------- merged MLP launch: both branches in one grid ----------------
__global__ __launch_bounds__(128) void mlp_merged(
    const float* __restrict__ feats,
    const float* __restrict__ s00, const float* __restrict__ b00,
    const float* __restrict__ s01, const float* __restrict__ b01,
    const float* __restrict__ s10, const float* __restrict__ b10,
    const float* __restrict__ s11, const float* __restrict__ b11,
    float* __restrict__ outf)
{
  extern __shared__ char smraw[];
  if (blockIdx.x < NB*NP)
    mlp_body<16,32, 64, 0, 2,2, 2>(blockIdx.x,         smraw, feats,
                                   g_w0t, s00,b00, g_w0u, s01,b01, outf);
  else
    mlp_body<32,64,128,64, 4,4, 8>(blockIdx.x - NB*NP, smraw, feats,
                                   g_w1t, s10,b10, g_w1u, s11,b11, outf);
}

// smem: xin 36*32 + h1s 64*32 floats + sidx 32 ints + red 512 floats
#define MLP_SMEM ((36*32 + 64*32)*4 + 32*4 + 512*4)

// ---------------- launch ----------------
extern "C" void kernel_launch(void* const* d_in, const int* in_sizes, int n_in,
                              void* d_out, int out_size) {
  const float* xyz   = (const float*)d_in[0];
  const float* feats = (const float*)d_in[1];
  const float* w00 = (const float*)d_in[2];
  const float* s00 = (const float*)d_in[3];
  const float* b00 = (const float*)d_in[4];
  const float* w01 = (const float*)d_in[5];
  const float* s01 = (const float*)d_in[6];
  const float* b01 = (const float*)d_in[7];
  const float* w10 = (const float*)d_in[8];
  const float* s10 = (const float*)d_in[9];
  const float* b10 = (const float*)d_in[10];
  const float* w11 = (const float*)d_in[11];
  const float* s11 = (const float*)d_in[12];
  const float* b11 = (const float*)d_in[13];
  float* out = (float*)d_out;

  prep_kernel<<<(NB*NPTS+255)/256, 256>>>(xyz, w00, w01, w10, w11);
  fps_kernel<<<NB*CSZ, FTH>>>(out);                    // writes new_xyz (B,P,3)
  ballquery_kernel<<<(NB*NP)/8, 256>>>();
  float* outf = out + NB*NP*3;                         // features (B,192,P)
  mlp_merged<<<2*NB*NP, 128, MLP_SMEM>>>(feats, s00,b00, s01,b01,
                                         s10,b10, s11,b11, outf);
}